// round 3
// baseline (speedup 1.0000x reference)
#include <cuda_runtime.h>
#include <cstdint>
#include <cstddef>

// Problem constants
#define TB_   128
#define NSEQ  196
#define CDIM  512
#define HDIM  2048
#define TSTEP 4
#define BB    32
#define MROWS (TB_*NSEQ)          // 25088 (divisible by 128: 196 tiles)
#define SLAB1 (NSEQ*HDIM)         // 401408
#define SLAB2 (NSEQ*CDIM)         // 100352

// ---------------- scratch (device globals; no runtime allocation) ----------
__device__ float  g_h1[(size_t)MROWS*HDIM];   // GEMM1 output (TB,N,H)
__device__ float  g_s1[(size_t)MROWS*HDIM];   // layer-1 spikes, natural (t,b,n,h)
__device__ float  g_o2[(size_t)MROWS*CDIM];   // GEMM2 output (TB,N,C)
__device__ float  g_s2[(size_t)MROWS*CDIM];   // layer-2 spikes, natural (t,b,n,c)
__device__ double g_sum1[HDIM], g_sq1[HDIM];
__device__ double g_sum2[CDIM], g_sq2[CDIM];
__device__ float  g_mean1[HDIM], g_rstd1[HDIM];
__device__ float  g_mean2[CDIM], g_rstd2[CDIM];

// ---------------- packed f32x2 helpers -------------------------------------
__device__ __forceinline__ void ffma2(unsigned long long &d,
                                      unsigned long long a,
                                      unsigned long long b)
{
    asm("fma.rn.f32x2 %0, %1, %2, %3;" : "=l"(d) : "l"(a), "l"(b), "l"(d));
}

__device__ __forceinline__ unsigned long long dup2(float v)
{
    unsigned long long r;
    asm("mov.b64 %0, {%1, %1};" : "=l"(r) : "f"(v));
    return r;
}

// ---------------- zero the stat accumulators (per launch) ------------------
__global__ void zero_stats_kernel() {
    int i = blockIdx.x * blockDim.x + threadIdx.x;
    if (i < HDIM) { g_sum1[i] = 0.0; g_sq1[i] = 0.0; }
    if (i < CDIM) { g_sum2[i] = 0.0; g_sq2[i] = 0.0; }
}

// ---------------- SGEMM (FFMA2): C[M,NN] = A[M,K] * B[NN,K]^T --------------
// SECOND=false: A = x (row-major, lda=512), B = w1 (2048x512), C = g_h1
// SECOND=true : A = spikes with permuted addressing
//               A(r,k) = g_s1[(r/196)*401408 + k*196 + (r%196)], B = w2, C = g_o2
#define BM 128
#define BN 128
#define BK 16

template<bool SECOND>
__global__ __launch_bounds__(256, 2)
void sgemm_kernel(const float* __restrict__ Ain, const float* __restrict__ B)
{
    constexpr int K  = SECOND ? HDIM : CDIM;
    constexpr int NN = SECOND ? CDIM : HDIM;
    const float* __restrict__ A = SECOND ? g_s1 : Ain;
    float* __restrict__ C = SECOND ? g_o2 : g_h1;

    // A tile stored duplicated: Asd[k][2m] == Asd[k][2m+1] == A(m0+m, k0+k)
    __shared__ __align__(16) float Asd[BK][2 * BM];
    __shared__ __align__(16) float Bs[BK][BN];

    const int tid = threadIdx.x;
    const int m0 = blockIdx.y * BM;
    const int n0 = blockIdx.x * BN;
    const int tx = tid & 15;   // 0..15 -> owns cols {tx*4..+3} and {64+tx*4..+3}
    const int ty = tid >> 4;   // 0..15 -> owns rows ty*8..ty*8+7

    unsigned long long acc[8][4];
#pragma unroll
    for (int i = 0; i < 8; i++)
#pragma unroll
        for (int p = 0; p < 4; p++) acc[i][p] = 0ull;

    // -------- global-load addressing --------
    const int ar = tid >> 2;          // 0..63 (row within tile, +64 for 2nd)
    const int ac = (tid & 3) << 2;    // 0,4,8,12 (k offset)
    const int arow = tid & 127;       // SECOND: row of A tile this thread fills
    const int kb = (tid >> 7) << 3;   // SECOND: 0 or 8 (k offset)
    const float* aptr2 = nullptr;
    if (SECOND) {
        int r  = m0 + arow;
        int tb = r / NSEQ;
        int n  = r - tb * NSEQ;
        aptr2 = A + (size_t)tb * SLAB1 + n;
    }

    // -------- prefetch registers --------
    float4 pa0, pa1, pb0, pb1;
    float  pa2[8];

    auto gload = [&](int k0) {
        if (!SECOND) {
            pa0 = *(const float4*)(A + (size_t)(m0 + ar) * K + k0 + ac);
            pa1 = *(const float4*)(A + (size_t)(m0 + ar + 64) * K + k0 + ac);
        } else {
#pragma unroll
            for (int j = 0; j < 8; j++)
                pa2[j] = aptr2[(size_t)(k0 + kb + j) * NSEQ];
        }
        pb0 = *(const float4*)(B + (size_t)(n0 + ar) * K + k0 + ac);
        pb1 = *(const float4*)(B + (size_t)(n0 + ar + 64) * K + k0 + ac);
    };

    auto sstore = [&]() {
        if (!SECOND) {
            *(unsigned long long*)&Asd[ac + 0][2 * ar] = dup2(pa0.x);
            *(unsigned long long*)&Asd[ac + 1][2 * ar] = dup2(pa0.y);
            *(unsigned long long*)&Asd[ac + 2][2 * ar] = dup2(pa0.z);
            *(unsigned long long*)&Asd[ac + 3][2 * ar] = dup2(pa0.w);
            *(unsigned long long*)&Asd[ac + 0][2 * (ar + 64)] = dup2(pa1.x);
            *(unsigned long long*)&Asd[ac + 1][2 * (ar + 64)] = dup2(pa1.y);
            *(unsigned long long*)&Asd[ac + 2][2 * (ar + 64)] = dup2(pa1.z);
            *(unsigned long long*)&Asd[ac + 3][2 * (ar + 64)] = dup2(pa1.w);
        } else {
#pragma unroll
            for (int j = 0; j < 8; j++)
                *(unsigned long long*)&Asd[kb + j][2 * arow] = dup2(pa2[j]);
        }
        Bs[ac + 0][ar] = pb0.x; Bs[ac + 1][ar] = pb0.y;
        Bs[ac + 2][ar] = pb0.z; Bs[ac + 3][ar] = pb0.w;
        Bs[ac + 0][ar + 64] = pb1.x; Bs[ac + 1][ar + 64] = pb1.y;
        Bs[ac + 2][ar + 64] = pb1.z; Bs[ac + 3][ar + 64] = pb1.w;
    };

    gload(0);
    sstore();
    __syncthreads();

    for (int k0 = 0; k0 < K; k0 += BK) {
        const bool has_next = (k0 + BK) < K;
        if (has_next) gload(k0 + BK);

#pragma unroll
        for (int k = 0; k < BK; k++) {
            unsigned long long a2[8], b2[4];
            const ulonglong2* ap = (const ulonglong2*)&Asd[k][ty * 16];
#pragma unroll
            for (int i = 0; i < 4; i++) {
                ulonglong2 t = ap[i];
                a2[2 * i] = t.x; a2[2 * i + 1] = t.y;
            }
            ulonglong2 bq0 = *(const ulonglong2*)&Bs[k][tx * 4];
            ulonglong2 bq1 = *(const ulonglong2*)&Bs[k][64 + tx * 4];
            b2[0] = bq0.x; b2[1] = bq0.y; b2[2] = bq1.x; b2[3] = bq1.y;
#pragma unroll
            for (int i = 0; i < 8; i++)
#pragma unroll
                for (int p = 0; p < 4; p++)
                    ffma2(acc[i][p], a2[i], b2[p]);
        }

        if (has_next) {
            __syncthreads();
            sstore();
            __syncthreads();
        }
    }

    // ---- write C: two float4-equivalents per row ----
#pragma unroll
    for (int i = 0; i < 8; i++) {
        int r = m0 + ty * 8 + i;
        float* cr = C + (size_t)r * NN + n0;
        ulonglong2 v0; v0.x = acc[i][0]; v0.y = acc[i][1];
        ulonglong2 v1; v1.x = acc[i][2]; v1.y = acc[i][3];
        *(ulonglong2*)(cr + tx * 4) = v0;
        *(ulonglong2*)(cr + 64 + tx * 4) = v1;
    }
}

// ---------------- BN stats: per-channel sum / sumsq over 25088 rows --------
template<bool SECOND>
__global__ __launch_bounds__(256)
void bn_stats_kernel()
{
    constexpr int CH  = SECOND ? CDIM : HDIM;
    constexpr int PER = CH / 256;
    const float* __restrict__ X = SECOND ? g_o2 : g_h1;
    double* __restrict__ SUM = SECOND ? g_sum2 : g_sum1;
    double* __restrict__ SQ  = SECOND ? g_sq2  : g_sq1;

    float s[PER], q[PER];
#pragma unroll
    for (int j = 0; j < PER; j++) { s[j] = 0.f; q[j] = 0.f; }

    const int c0 = threadIdx.x;
    const float* base = X + (size_t)blockIdx.x * 128 * CH;  // 196 blocks * 128 rows
    for (int r = 0; r < 128; r++) {
        const float* row = base + (size_t)r * CH;
#pragma unroll
        for (int j = 0; j < PER; j++) {
            float v = row[c0 + j * 256];
            s[j] += v;
            q[j] = fmaf(v, v, q[j]);
        }
    }
#pragma unroll
    for (int j = 0; j < PER; j++) {
        atomicAdd(&SUM[c0 + j * 256], (double)s[j]);
        atomicAdd(&SQ[c0 + j * 256],  (double)q[j]);
    }
}

template<bool SECOND>
__global__ void bn_final_kernel()
{
    constexpr int CH = SECOND ? CDIM : HDIM;
    const double* SUM = SECOND ? g_sum2 : g_sum1;
    const double* SQ  = SECOND ? g_sq2  : g_sq1;
    float* MEAN = SECOND ? g_mean2 : g_mean1;
    float* RSTD = SECOND ? g_rstd2 : g_rstd1;
    int c = blockIdx.x * blockDim.x + threadIdx.x;
    if (c < CH) {
        const double inv_n = 1.0 / (double)MROWS;
        double m   = SUM[c] * inv_n;
        double var = SQ[c] * inv_n - m * m;
        MEAN[c] = (float)m;
        RSTD[c] = rsqrtf((float)var + 1e-5f);
    }
}

// ---------------- BN affine + 4-step LIF, emit binary spikes ---------------
// LIF: v += (x - v)/2; spike = (v >= 1); hard reset to 0.
template<bool SECOND>
__global__ __launch_bounds__(256)
void lif_kernel(const float* __restrict__ gamma, const float* __restrict__ beta)
{
    constexpr int CH   = SECOND ? CDIM : HDIM;
    constexpr int SLAB = NSEQ * CH;
    const float* __restrict__ X = SECOND ? g_o2 : g_h1;
    float* __restrict__ S = SECOND ? g_s2 : g_s1;
    const float* __restrict__ MEAN = SECOND ? g_mean2 : g_mean1;
    const float* __restrict__ RSTD = SECOND ? g_rstd2 : g_rstd1;

    size_t tid = (size_t)blockIdx.x * blockDim.x + threadIdx.x;
    int c = (int)(tid % CH);
    size_t rest = tid / CH;
    int n = (int)(rest % NSEQ);
    int b = (int)(rest / NSEQ);

    float m  = MEAN[c];
    float r  = RSTD[c];
    float gm = gamma[c];
    float bt = beta[c];

    float v = 0.f;
#pragma unroll
    for (int t = 0; t < TSTEP; t++) {
        size_t tb = (size_t)(t * BB + b);
        float x  = X[(tb * NSEQ + n) * CH + c];
        // match reference op order: gamma*(x-mean)*rstd + beta (no FMA fusion)
        float xn = __fadd_rn(__fmul_rn(__fmul_rn(gm, __fsub_rn(x, m)), r), bt);
        v = __fadd_rn(v, __fmul_rn(__fsub_rn(xn, v), 0.5f));
        float sp = (v >= 1.0f) ? 1.0f : 0.0f;
        S[tb * SLAB + (size_t)n * CH + c] = sp;
        if (v >= 1.0f) v = 0.f;   // hard reset (detached)
    }
}

// ---------------- final permuted write: out[tb][j*512+i] = s2[tb][i*196+j] -
__global__ void transpose_out_kernel(float* __restrict__ out)
{
    __shared__ float tile[32][33];
    int tb = blockIdx.z;
    int i0 = blockIdx.y * 32;   // i over 512
    int j0 = blockIdx.x * 32;   // j over 196
    const float* src = g_s2 + (size_t)tb * SLAB2;
    float* dst = out + (size_t)tb * SLAB2;
    int x = threadIdx.x, y = threadIdx.y;   // block (32,8)

#pragma unroll
    for (int yy = y; yy < 32; yy += 8) {
        int i = i0 + yy, j = j0 + x;
        if (j < NSEQ) tile[yy][x] = src[(size_t)i * NSEQ + j];
    }
    __syncthreads();
#pragma unroll
    for (int yy = y; yy < 32; yy += 8) {
        int j = j0 + yy, i = i0 + x;
        if (j < NSEQ) dst[(size_t)j * CDIM + i] = tile[x][yy];
    }
}

// ---------------- launch --------------------------------------------------
extern "C" void kernel_launch(void* const* d_in, const int* in_sizes, int n_in,
                              void* d_out, int out_size)
{
    const float* x  = (const float*)d_in[0];
    const float* w1 = (const float*)d_in[1];
    const float* g1 = (const float*)d_in[2];
    const float* b1 = (const float*)d_in[3];
    const float* w2 = (const float*)d_in[4];
    const float* g2 = (const float*)d_in[5];
    const float* b2 = (const float*)d_in[6];
    float* out = (float*)d_out;

    zero_stats_kernel<<<8, 256>>>();

    // Layer 1: x(25088x512) @ w1^T(512x2048) -> g_h1
    sgemm_kernel<false><<<dim3(HDIM / BN, MROWS / BM), 256>>>(x, w1);
    bn_stats_kernel<false><<<MROWS / 128, 256>>>();
    bn_final_kernel<false><<<HDIM / 256, 256>>>();
    lif_kernel<false><<<(BB * NSEQ * HDIM) / 256, 256>>>(g1, b1);

    // Layer 2: permuted-spikes(25088x2048) @ w2^T(2048x512) -> g_o2
    sgemm_kernel<true><<<dim3(CDIM / BN, MROWS / BM), 256>>>(nullptr, w2);
    bn_stats_kernel<true><<<MROWS / 128, 256>>>();
    bn_final_kernel<true><<<CDIM / 256, 256>>>();
    lif_kernel<true><<<(BB * NSEQ * CDIM) / 256, 256>>>(g2, b2);

    // Final flat-reshape permutation into d_out
    transpose_out_kernel<<<dim3(7, CDIM / 32, TB_), dim3(32, 8)>>>(out);
}

// round 8
// speedup vs baseline: 1.6005x; 1.6005x over previous
#include <cuda_runtime.h>
#include <cstdint>
#include <cstddef>

// Problem constants
#define TB_   128
#define NSEQ  196
#define CDIM  512
#define HDIM  2048
#define TSTEP 4
#define BB    32
#define MROWS (TB_*NSEQ)          // 25088
#define SLAB1 (NSEQ*HDIM)         // 401408
#define SLAB2 (NSEQ*CDIM)         // 100352
#define NWORD 64                  // 2048 bits per GEMM2 row

// ---------------- scratch (device globals) ---------------------------------
__device__ float    g_h1[(size_t)MROWS*HDIM];   // GEMM1 out (tb*196+n, h)
__device__ float    g_o2[(size_t)MROWS*CDIM];   // GEMM2 out (tb*196+j, c)
__device__ float    g_s2[(size_t)MROWS*CDIM];   // layer-2 spikes
__device__ uint32_t g_mask[(size_t)MROWS*NWORD]; // spike bitmask per GEMM2 row
__device__ float    g_w2T[(size_t)HDIM*CDIM];   // w2 transposed [k][c]
__device__ double   g_sum1[HDIM], g_sq1[HDIM];
__device__ double   g_sum2[CDIM], g_sq2[CDIM];
__device__ float    g_mean1[HDIM], g_rstd1[HDIM];
__device__ float    g_mean2[CDIM], g_rstd2[CDIM];

// ---------------- zero stats + mask (per launch; graph-replayable) ---------
__global__ void zero_stats_kernel() {
    int i = blockIdx.x * blockDim.x + threadIdx.x;
    if (i < HDIM) { g_sum1[i] = 0.0; g_sq1[i] = 0.0; }
    if (i < CDIM) { g_sum2[i] = 0.0; g_sq2[i] = 0.0; }
}
__global__ void zero_mask_kernel() {
    size_t i = (size_t)blockIdx.x * blockDim.x + threadIdx.x;
    if (i < (size_t)MROWS * NWORD) g_mask[i] = 0u;
}

// ---------------- w2 (512x2048) -> w2T (2048x512) --------------------------
__global__ void transpose_w2_kernel(const float* __restrict__ w2)
{
    __shared__ float t[32][33];
    int k0 = blockIdx.x * 32, c0 = blockIdx.y * 32;
    int x = threadIdx.x, y = threadIdx.y;     // block (32,8)
#pragma unroll
    for (int yy = y; yy < 32; yy += 8)
        t[yy][x] = w2[(size_t)(c0 + yy) * HDIM + k0 + x];
    __syncthreads();
#pragma unroll
    for (int yy = y; yy < 32; yy += 8)
        g_w2T[(size_t)(k0 + yy) * CDIM + c0 + x] = t[x][yy];
}

// ---------------- GEMM1 (fp32 SIMT, bitwise == cublas chain) ---------------
// C[M,H] = x[M,512] * w1[H,512]^T ; 128x128 tile, BK=16, 8x8 per thread.
#define BM 128
#define BN 128
#define BK 16

__global__ __launch_bounds__(256)
void sgemm1_kernel(const float* __restrict__ A, const float* __restrict__ B)
{
    constexpr int K  = CDIM;
    constexpr int NN = HDIM;
    float* __restrict__ C = g_h1;

    __shared__ float As[BK][BM];
    __shared__ float Bs[BK][BN];

    const int tid = threadIdx.x;
    const int m0 = blockIdx.y * BM;
    const int n0 = blockIdx.x * BN;
    const int tx = tid & 15;
    const int ty = tid >> 4;

    float acc[8][8];
#pragma unroll
    for (int i = 0; i < 8; i++)
#pragma unroll
        for (int j = 0; j < 8; j++) acc[i][j] = 0.f;

    for (int k0 = 0; k0 < K; k0 += BK) {
        int ar = tid >> 2;
        int ac = (tid & 3) * 4;
#pragma unroll
        for (int i = 0; i < 2; i++) {
            int row = ar + i * 64;
            float4 v = *(const float4*)(A + (size_t)(m0 + row) * K + k0 + ac);
            As[ac + 0][row] = v.x; As[ac + 1][row] = v.y;
            As[ac + 2][row] = v.z; As[ac + 3][row] = v.w;
            float4 w = *(const float4*)(B + (size_t)(n0 + row) * K + k0 + ac);
            Bs[ac + 0][row] = w.x; Bs[ac + 1][row] = w.y;
            Bs[ac + 2][row] = w.z; Bs[ac + 3][row] = w.w;
        }
        __syncthreads();

#pragma unroll
        for (int k = 0; k < BK; k++) {
            float a[8], b[8];
#pragma unroll
            for (int i = 0; i < 8; i++) a[i] = As[k][ty * 8 + i];
#pragma unroll
            for (int j = 0; j < 8; j++) b[j] = Bs[k][tx * 8 + j];
#pragma unroll
            for (int i = 0; i < 8; i++)
#pragma unroll
                for (int j = 0; j < 8; j++)
                    acc[i][j] = fmaf(a[i], b[j], acc[i][j]);
        }
        __syncthreads();
    }

#pragma unroll
    for (int i = 0; i < 8; i++) {
        int r = m0 + ty * 8 + i;
        float* cr = C + (size_t)r * NN + n0 + tx * 8;
#pragma unroll
        for (int j = 0; j < 8; j += 4)
            *(float4*)(cr + j) = make_float4(acc[i][j], acc[i][j+1],
                                             acc[i][j+2], acc[i][j+3]);
    }
}

// ---------------- BN stats / final -----------------------------------------
template<bool SECOND>
__global__ __launch_bounds__(256)
void bn_stats_kernel()
{
    constexpr int CH  = SECOND ? CDIM : HDIM;
    constexpr int PER = CH / 256;
    const float* __restrict__ X = SECOND ? g_o2 : g_h1;
    double* __restrict__ SUM = SECOND ? g_sum2 : g_sum1;
    double* __restrict__ SQ  = SECOND ? g_sq2  : g_sq1;

    float s[PER], q[PER];
#pragma unroll
    for (int j = 0; j < PER; j++) { s[j] = 0.f; q[j] = 0.f; }
    const int c0 = threadIdx.x;
    const float* base = X + (size_t)blockIdx.x * 128 * CH;
    for (int r = 0; r < 128; r++) {
        const float* row = base + (size_t)r * CH;
#pragma unroll
        for (int j = 0; j < PER; j++) {
            float v = row[c0 + j * 256];
            s[j] += v;
            q[j] = fmaf(v, v, q[j]);
        }
    }
#pragma unroll
    for (int j = 0; j < PER; j++) {
        atomicAdd(&SUM[c0 + j * 256], (double)s[j]);
        atomicAdd(&SQ[c0 + j * 256],  (double)q[j]);
    }
}

template<bool SECOND>
__global__ void bn_final_kernel()
{
    constexpr int CH = SECOND ? CDIM : HDIM;
    const double* SUM = SECOND ? g_sum2 : g_sum1;
    const double* SQ  = SECOND ? g_sq2  : g_sq1;
    float* MEAN = SECOND ? g_mean2 : g_mean1;
    float* RSTD = SECOND ? g_rstd2 : g_rstd1;
    int c = blockIdx.x * blockDim.x + threadIdx.x;
    if (c < CH) {
        const double inv_n = 1.0 / (double)MROWS;
        double m   = SUM[c] * inv_n;
        double var = SQ[c] * inv_n - m * m;
        MEAN[c] = (float)m;
        RSTD[c] = rsqrtf((float)var + 1e-5f);
    }
}

// ---------------- LIF layer 1 -> spike bitmask -----------------------------
// spike at (t,b,n,c): f=n*2048+c, k=f/196, j=f%196; row = (t*32+b)*196+j.
__global__ __launch_bounds__(256)
void lif1_kernel(const float* __restrict__ gamma, const float* __restrict__ beta)
{
    size_t tid = (size_t)blockIdx.x * blockDim.x + threadIdx.x;
    int c = (int)(tid % HDIM);
    size_t rest = tid / HDIM;
    int n = (int)(rest % NSEQ);
    int b = (int)(rest / NSEQ);

    float m  = g_mean1[c];
    float r  = g_rstd1[c];
    float gm = gamma[c];
    float bt = beta[c];

    int f = n * HDIM + c;
    int k = f / NSEQ;
    int j = f - k * NSEQ;
    uint32_t bit  = 1u << (k & 31);
    int      word = k >> 5;

    float v = 0.f;
#pragma unroll
    for (int t = 0; t < TSTEP; t++) {
        int tb = t * BB + b;
        float x  = g_h1[((size_t)tb * NSEQ + n) * HDIM + c];
        float xn = __fadd_rn(__fmul_rn(__fmul_rn(gm, __fsub_rn(x, m)), r), bt);
        v = __fadd_rn(v, __fmul_rn(__fsub_rn(xn, v), 0.5f));
        if (v >= 1.0f) {
            atomicOr(&g_mask[(size_t)(tb * NSEQ + j) * NWORD + word], bit);
            v = 0.f;
        }
    }
}

// ---------------- sparse GEMM2: o2[r][c] = sum_{k active} w2T[k][c] --------
// Bitwise == reference: fma(0,w,acc)==acc, fma(1,w,acc)==rn(acc+w), k ascend.
#define RPC 8
__global__ __launch_bounds__(512)
void gemm2_sparse_kernel()
{
    __shared__ uint32_t wbits[NWORD];
    __shared__ uint16_t klist[HDIM];
    __shared__ uint16_t excl[NWORD];
    __shared__ int warpsum[2];
    __shared__ int s_knum;

    const int tid = threadIdx.x;     // c = tid (0..511)
    const int row0 = blockIdx.x * RPC;

    for (int rr = 0; rr < RPC; rr++) {
        const int row = row0 + rr;
        if (tid < NWORD) wbits[tid] = g_mask[(size_t)row * NWORD + tid];
        __syncthreads();

        if (tid < NWORD) {
            uint32_t mw = wbits[tid];
            int cnt = __popc(mw);
            int incl = cnt;
#pragma unroll
            for (int d = 1; d < 32; d <<= 1) {
                int vv = __shfl_up_sync(0xffffffffu, incl, d);
                if ((tid & 31) >= d) incl += vv;
            }
            excl[tid] = (uint16_t)(incl - cnt);
            if ((tid & 31) == 31) warpsum[tid >> 5] = incl;
        }
        __syncthreads();

        if (tid < NWORD) {
            int off = excl[tid] + ((tid >= 32) ? warpsum[0] : 0);
            uint32_t mw = wbits[tid];
            int kb = tid * 32;
            while (mw) {
                int b = __ffs(mw) - 1;
                mw &= mw - 1;
                klist[off++] = (uint16_t)(kb + b);
            }
            if (tid == 63) s_knum = warpsum[0] + warpsum[1];
        }
        __syncthreads();

        const int knum = s_knum;
        float acc = 0.f;
        int i = 0;
        for (; i + 4 <= knum; i += 4) {
            int k0 = klist[i], k1 = klist[i+1], k2 = klist[i+2], k3 = klist[i+3];
            float v0 = g_w2T[(size_t)k0 * CDIM + tid];
            float v1 = g_w2T[(size_t)k1 * CDIM + tid];
            float v2 = g_w2T[(size_t)k2 * CDIM + tid];
            float v3 = g_w2T[(size_t)k3 * CDIM + tid];
            acc = __fadd_rn(acc, v0);
            acc = __fadd_rn(acc, v1);
            acc = __fadd_rn(acc, v2);
            acc = __fadd_rn(acc, v3);
        }
        for (; i < knum; i++)
            acc = __fadd_rn(acc, g_w2T[(size_t)klist[i] * CDIM + tid]);

        g_o2[(size_t)row * CDIM + tid] = acc;
        __syncthreads();
    }
}

// ---------------- LIF layer 2 (fp32 spikes) --------------------------------
__global__ __launch_bounds__(256)
void lif2_kernel(const float* __restrict__ gamma, const float* __restrict__ beta)
{
    size_t tid = (size_t)blockIdx.x * blockDim.x + threadIdx.x;
    int c = (int)(tid % CDIM);
    size_t rest = tid / CDIM;
    int n = (int)(rest % NSEQ);
    int b = (int)(rest / NSEQ);

    float m  = g_mean2[c];
    float r  = g_rstd2[c];
    float gm = gamma[c];
    float bt = beta[c];

    float v = 0.f;
#pragma unroll
    for (int t = 0; t < TSTEP; t++) {
        size_t tb = (size_t)(t * BB + b);
        float x  = g_o2[(tb * NSEQ + n) * CDIM + c];
        float xn = __fadd_rn(__fmul_rn(__fmul_rn(gm, __fsub_rn(x, m)), r), bt);
        v = __fadd_rn(v, __fmul_rn(__fsub_rn(xn, v), 0.5f));
        float sp = (v >= 1.0f) ? 1.0f : 0.0f;
        g_s2[tb * SLAB2 + (size_t)n * CDIM + c] = sp;
        if (v >= 1.0f) v = 0.f;
    }
}

// ---------------- final permuted write -------------------------------------
__global__ void transpose_out_kernel(float* __restrict__ out)
{
    __shared__ float tile[32][33];
    int tb = blockIdx.z;
    int i0 = blockIdx.y * 32;
    int j0 = blockIdx.x * 32;
    const float* src = g_s2 + (size_t)tb * SLAB2;
    float* dst = out + (size_t)tb * SLAB2;
    int x = threadIdx.x, y = threadIdx.y;

#pragma unroll
    for (int yy = y; yy < 32; yy += 8) {
        int i = i0 + yy, j = j0 + x;
        if (j < NSEQ) tile[yy][x] = src[(size_t)i * NSEQ + j];
    }
    __syncthreads();
#pragma unroll
    for (int yy = y; yy < 32; yy += 8) {
        int j = j0 + yy, i = i0 + x;
        if (j < NSEQ) dst[(size_t)j * CDIM + i] = tile[x][yy];
    }
}

// ---------------- launch ----------------------------------------------------
extern "C" void kernel_launch(void* const* d_in, const int* in_sizes, int n_in,
                              void* d_out, int out_size)
{
    const float* x  = (const float*)d_in[0];
    const float* w1 = (const float*)d_in[1];
    const float* g1 = (const float*)d_in[2];
    const float* b1 = (const float*)d_in[3];
    const float* w2 = (const float*)d_in[4];
    const float* g2 = (const float*)d_in[5];
    const float* b2 = (const float*)d_in[6];
    float* out = (float*)d_out;

    zero_stats_kernel<<<8, 256>>>();
    zero_mask_kernel<<<((size_t)MROWS * NWORD + 1023) / 1024, 1024>>>();
    transpose_w2_kernel<<<dim3(HDIM / 32, CDIM / 32), dim3(32, 8)>>>(w2);

    // Layer 1: fp32 SIMT GEMM (bitwise chain) -> g_h1
    sgemm1_kernel<<<dim3(HDIM / BN, MROWS / BM), 256>>>(x, w1);
    bn_stats_kernel<false><<<MROWS / 128, 256>>>();
    bn_final_kernel<false><<<HDIM / 256, 256>>>();
    lif1_kernel<<<((size_t)BB * NSEQ * HDIM) / 256, 256>>>(g1, b1);

    // Layer 2: sparse spike GEMM (exact no-op elision) -> g_o2
    gemm2_sparse_kernel<<<MROWS / RPC, 512>>>();
    bn_stats_kernel<true><<<MROWS / 128, 256>>>();
    bn_final_kernel<true><<<CDIM / 256, 256>>>();
    lif2_kernel<<<((size_t)BB * NSEQ * CDIM) / 256, 256>>>(g2, b2);

    transpose_out_kernel<<<dim3(7, CDIM / 32, TB_), dim3(32, 8)>>>(out);
}

// round 9
// speedup vs baseline: 1.7923x; 1.1199x over previous
#include <cuda_runtime.h>
#include <cstdint>
#include <cstddef>

// Problem constants
#define TB_   128
#define NSEQ  196
#define CDIM  512
#define HDIM  2048
#define TSTEP 4
#define BB    32
#define MROWS (TB_*NSEQ)          // 25088
#define SLAB1 (NSEQ*HDIM)         // 401408
#define SLAB2 (NSEQ*CDIM)         // 100352
#define NWORD 64                  // 2048 bits per GEMM2 row

// ---------------- scratch (device globals) ---------------------------------
__device__ float    g_h1[(size_t)MROWS*HDIM];   // GEMM1 out (tb*196+n, h)
__device__ float    g_o2[(size_t)MROWS*CDIM];   // GEMM2 out (tb*196+j, c)
__device__ float    g_s2[(size_t)MROWS*CDIM];   // layer-2 spikes
__device__ uint32_t g_mask[(size_t)MROWS*NWORD]; // spike bitmask per GEMM2 row
__device__ float    g_w2T[(size_t)HDIM*CDIM];   // w2 transposed [k][c]
__device__ float    g_xT [(size_t)CDIM*MROWS];  // x transposed  [k][m]
__device__ float    g_w1T[(size_t)CDIM*HDIM];   // w1 transposed [k][h]
__device__ double   g_sum1[HDIM], g_sq1[HDIM];
__device__ double   g_sum2[CDIM], g_sq2[CDIM];
__device__ float    g_mean1[HDIM], g_rstd1[HDIM];
__device__ float    g_mean2[CDIM], g_rstd2[CDIM];

// ---------------- PTX helpers ----------------------------------------------
__device__ __forceinline__ uint32_t smem_u32(const void* p) {
    uint32_t a;
    asm("{ .reg .u64 t; cvta.to.shared.u64 t, %1; cvt.u32.u64 %0, t; }" : "=r"(a) : "l"(p));
    return a;
}
#define CP_ASYNC16(dst, src) \
    asm volatile("cp.async.cg.shared.global [%0], [%1], 16;" :: "r"(dst), "l"(src))
#define CP_COMMIT() asm volatile("cp.async.commit_group;")
#define CP_WAIT(n)  asm volatile("cp.async.wait_group %0;" :: "n"(n))

// ---------------- zero stats + mask (per launch; graph-replayable) ---------
__global__ void zero_stats_kernel() {
    int i = blockIdx.x * blockDim.x + threadIdx.x;
    if (i < HDIM) { g_sum1[i] = 0.0; g_sq1[i] = 0.0; }
    if (i < CDIM) { g_sum2[i] = 0.0; g_sq2[i] = 0.0; }
}
__global__ void zero_mask_kernel() {
    size_t i = (size_t)blockIdx.x * blockDim.x + threadIdx.x;
    if (i < (size_t)MROWS * NWORD) g_mask[i] = 0u;
}

// ---------------- generic 32x32 tile transpose: dst[c][r] = src[r][c] ------
__global__ void transpose_rc_kernel(const float* __restrict__ src,
                                    float* __restrict__ dst, int R, int C)
{
    __shared__ float t[32][33];
    int r0 = blockIdx.x * 32, c0 = blockIdx.y * 32;
    int x = threadIdx.x, y = threadIdx.y;     // block (32,8)
#pragma unroll
    for (int yy = y; yy < 32; yy += 8)
        t[yy][x] = src[(size_t)(r0 + yy) * C + c0 + x];
    __syncthreads();
#pragma unroll
    for (int yy = y; yy < 32; yy += 8)
        dst[(size_t)(c0 + yy) * R + r0 + x] = t[x][yy];
}

// ---------------- GEMM1: cp.async double-buffered fp32 SIMT ----------------
// C[M,H] = x[M,512] * w1[H,512]^T, bitwise == ascending-k FMA chain.
// Inputs pre-transposed to k-major: g_xT[k][m], g_w1T[k][h].
#define BM 128
#define BN 128
#define BK 16
#define NIT (CDIM / BK)   // 32

__global__ __launch_bounds__(256, 2)
void sgemm1_kernel()
{
    __shared__ float As[2][BK][BM];   // 16 KB
    __shared__ float Bs[2][BK][BN];   // 16 KB

    const int tid = threadIdx.x;
    const int m0 = blockIdx.y * BM;
    const int n0 = blockIdx.x * BN;
    const int tx = tid & 15;
    const int ty = tid >> 4;

    float acc[8][8];
#pragma unroll
    for (int i = 0; i < 8; i++)
#pragma unroll
        for (int j = 0; j < 8; j++) acc[i][j] = 0.f;

    // chunk decomposition: 16 k-rows x 32 chunks(16B) = 512 chunks per matrix
    const int ck = tid >> 5;          // k-row for this thread's chunks
    const int cc = (tid & 31) * 4;    // float offset within row

    auto load_stage = [&](int s, int k0) {
#pragma unroll
        for (int i = 0; i < 2; i++) {
            int k = ck + i * 8;
            CP_ASYNC16(smem_u32(&As[s][k][cc]),
                       g_xT + (size_t)(k0 + k) * MROWS + m0 + cc);
        }
#pragma unroll
        for (int i = 0; i < 2; i++) {
            int k = ck + i * 8;
            CP_ASYNC16(smem_u32(&Bs[s][k][cc]),
                       g_w1T + (size_t)(k0 + k) * HDIM + n0 + cc);
        }
        CP_COMMIT();
    };

    load_stage(0, 0);

    for (int it = 0; it < NIT; it++) {
        const int cur = it & 1;
        if (it + 1 < NIT) {
            load_stage(cur ^ 1, (it + 1) * BK);
            CP_WAIT(1);
        } else {
            CP_WAIT(0);
        }
        __syncthreads();

#pragma unroll
        for (int k = 0; k < BK; k++) {
            float a[8], b[8];
#pragma unroll
            for (int i = 0; i < 8; i++) a[i] = As[cur][k][ty * 8 + i];
#pragma unroll
            for (int j = 0; j < 8; j++) b[j] = Bs[cur][k][tx * 8 + j];
#pragma unroll
            for (int i = 0; i < 8; i++)
#pragma unroll
                for (int j = 0; j < 8; j++)
                    acc[i][j] = fmaf(a[i], b[j], acc[i][j]);
        }
        __syncthreads();   // guard: next iter re-issues cp.async into buf cur^1's partner
    }

#pragma unroll
    for (int i = 0; i < 8; i++) {
        int r = m0 + ty * 8 + i;
        float* cr = g_h1 + (size_t)r * HDIM + n0 + tx * 8;
#pragma unroll
        for (int j = 0; j < 8; j += 4)
            *(float4*)(cr + j) = make_float4(acc[i][j], acc[i][j+1],
                                             acc[i][j+2], acc[i][j+3]);
    }
}

// ---------------- BN stats / final -----------------------------------------
template<bool SECOND>
__global__ __launch_bounds__(256)
void bn_stats_kernel()
{
    constexpr int CH  = SECOND ? CDIM : HDIM;
    constexpr int PER = CH / 256;
    const float* __restrict__ X = SECOND ? g_o2 : g_h1;
    double* __restrict__ SUM = SECOND ? g_sum2 : g_sum1;
    double* __restrict__ SQ  = SECOND ? g_sq2  : g_sq1;

    float s[PER], q[PER];
#pragma unroll
    for (int j = 0; j < PER; j++) { s[j] = 0.f; q[j] = 0.f; }
    const int c0 = threadIdx.x;
    const float* base = X + (size_t)blockIdx.x * 128 * CH;
    for (int r = 0; r < 128; r++) {
        const float* row = base + (size_t)r * CH;
#pragma unroll
        for (int j = 0; j < PER; j++) {
            float v = row[c0 + j * 256];
            s[j] += v;
            q[j] = fmaf(v, v, q[j]);
        }
    }
#pragma unroll
    for (int j = 0; j < PER; j++) {
        atomicAdd(&SUM[c0 + j * 256], (double)s[j]);
        atomicAdd(&SQ[c0 + j * 256],  (double)q[j]);
    }
}

template<bool SECOND>
__global__ void bn_final_kernel()
{
    constexpr int CH = SECOND ? CDIM : HDIM;
    const double* SUM = SECOND ? g_sum2 : g_sum1;
    const double* SQ  = SECOND ? g_sq2  : g_sq1;
    float* MEAN = SECOND ? g_mean2 : g_mean1;
    float* RSTD = SECOND ? g_rstd2 : g_rstd1;
    int c = blockIdx.x * blockDim.x + threadIdx.x;
    if (c < CH) {
        const double inv_n = 1.0 / (double)MROWS;
        double m   = SUM[c] * inv_n;
        double var = SQ[c] * inv_n - m * m;
        MEAN[c] = (float)m;
        RSTD[c] = rsqrtf((float)var + 1e-5f);
    }
}

// ---------------- LIF layer 1 -> spike bitmask -----------------------------
// spike at (t,b,n,c): f=n*2048+c, k=f/196, j=f%196; row = (t*32+b)*196+j.
__global__ __launch_bounds__(256)
void lif1_kernel(const float* __restrict__ gamma, const float* __restrict__ beta)
{
    size_t tid = (size_t)blockIdx.x * blockDim.x + threadIdx.x;
    int c = (int)(tid % HDIM);
    size_t rest = tid / HDIM;
    int n = (int)(rest % NSEQ);
    int b = (int)(rest / NSEQ);

    float m  = g_mean1[c];
    float r  = g_rstd1[c];
    float gm = gamma[c];
    float bt = beta[c];

    int f = n * HDIM + c;
    int k = f / NSEQ;
    int j = f - k * NSEQ;
    uint32_t bit  = 1u << (k & 31);
    int      word = k >> 5;

    float v = 0.f;
#pragma unroll
    for (int t = 0; t < TSTEP; t++) {
        int tb = t * BB + b;
        float x  = g_h1[((size_t)tb * NSEQ + n) * HDIM + c];
        float xn = __fadd_rn(__fmul_rn(__fmul_rn(gm, __fsub_rn(x, m)), r), bt);
        v = __fadd_rn(v, __fmul_rn(__fsub_rn(xn, v), 0.5f));
        if (v >= 1.0f) {
            atomicOr(&g_mask[(size_t)(tb * NSEQ + j) * NWORD + word], bit);
            v = 0.f;
        }
    }
}

// ---------------- sparse GEMM2: o2[r][c] = sum_{k active} w2T[k][c] --------
// Bitwise == reference: fma(0,w,acc)==acc, fma(1,w,acc)==rn(acc+w), k ascend.
#define RPC 8
__global__ __launch_bounds__(512)
void gemm2_sparse_kernel()
{
    __shared__ uint32_t wbits[NWORD];
    __shared__ uint16_t klist[HDIM];
    __shared__ uint16_t excl[NWORD];
    __shared__ int warpsum[2];
    __shared__ int s_knum;

    const int tid = threadIdx.x;     // c = tid (0..511)
    const int row0 = blockIdx.x * RPC;

    for (int rr = 0; rr < RPC; rr++) {
        const int row = row0 + rr;
        if (tid < NWORD) wbits[tid] = g_mask[(size_t)row * NWORD + tid];
        __syncthreads();

        if (tid < NWORD) {
            uint32_t mw = wbits[tid];
            int cnt = __popc(mw);
            int incl = cnt;
#pragma unroll
            for (int d = 1; d < 32; d <<= 1) {
                int vv = __shfl_up_sync(0xffffffffu, incl, d);
                if ((tid & 31) >= d) incl += vv;
            }
            excl[tid] = (uint16_t)(incl - cnt);
            if ((tid & 31) == 31) warpsum[tid >> 5] = incl;
        }
        __syncthreads();

        if (tid < NWORD) {
            int off = excl[tid] + ((tid >= 32) ? warpsum[0] : 0);
            uint32_t mw = wbits[tid];
            int kb = tid * 32;
            while (mw) {
                int b = __ffs(mw) - 1;
                mw &= mw - 1;
                klist[off++] = (uint16_t)(kb + b);
            }
            if (tid == 63) s_knum = warpsum[0] + warpsum[1];
        }
        __syncthreads();

        const int knum = s_knum;
        float acc = 0.f;
        int i = 0;
        for (; i + 4 <= knum; i += 4) {
            int k0 = klist[i], k1 = klist[i+1], k2 = klist[i+2], k3 = klist[i+3];
            float v0 = g_w2T[(size_t)k0 * CDIM + tid];
            float v1 = g_w2T[(size_t)k1 * CDIM + tid];
            float v2 = g_w2T[(size_t)k2 * CDIM + tid];
            float v3 = g_w2T[(size_t)k3 * CDIM + tid];
            acc = __fadd_rn(acc, v0);
            acc = __fadd_rn(acc, v1);
            acc = __fadd_rn(acc, v2);
            acc = __fadd_rn(acc, v3);
        }
        for (; i < knum; i++)
            acc = __fadd_rn(acc, g_w2T[(size_t)klist[i] * CDIM + tid]);

        g_o2[(size_t)row * CDIM + tid] = acc;
        __syncthreads();
    }
}

// ---------------- LIF layer 2 (fp32 spikes) --------------------------------
__global__ __launch_bounds__(256)
void lif2_kernel(const float* __restrict__ gamma, const float* __restrict__ beta)
{
    size_t tid = (size_t)blockIdx.x * blockDim.x + threadIdx.x;
    int c = (int)(tid % CDIM);
    size_t rest = tid / CDIM;
    int n = (int)(rest % NSEQ);
    int b = (int)(rest / NSEQ);

    float m  = g_mean2[c];
    float r  = g_rstd2[c];
    float gm = gamma[c];
    float bt = beta[c];

    float v = 0.f;
#pragma unroll
    for (int t = 0; t < TSTEP; t++) {
        size_t tb = (size_t)(t * BB + b);
        float x  = g_o2[(tb * NSEQ + n) * CDIM + c];
        float xn = __fadd_rn(__fmul_rn(__fmul_rn(gm, __fsub_rn(x, m)), r), bt);
        v = __fadd_rn(v, __fmul_rn(__fsub_rn(xn, v), 0.5f));
        float sp = (v >= 1.0f) ? 1.0f : 0.0f;
        g_s2[tb * SLAB2 + (size_t)n * CDIM + c] = sp;
        if (v >= 1.0f) v = 0.f;
    }
}

// ---------------- final permuted write -------------------------------------
__global__ void transpose_out_kernel(float* __restrict__ out)
{
    __shared__ float tile[32][33];
    int tb = blockIdx.z;
    int i0 = blockIdx.y * 32;
    int j0 = blockIdx.x * 32;
    const float* src = g_s2 + (size_t)tb * SLAB2;
    float* dst = out + (size_t)tb * SLAB2;
    int x = threadIdx.x, y = threadIdx.y;

#pragma unroll
    for (int yy = y; yy < 32; yy += 8) {
        int i = i0 + yy, j = j0 + x;
        if (j < NSEQ) tile[yy][x] = src[(size_t)i * NSEQ + j];
    }
    __syncthreads();
#pragma unroll
    for (int yy = y; yy < 32; yy += 8) {
        int j = j0 + yy, i = i0 + x;
        if (j < NSEQ) dst[(size_t)j * CDIM + i] = tile[x][yy];
    }
}

// ---------------- launch ----------------------------------------------------
extern "C" void kernel_launch(void* const* d_in, const int* in_sizes, int n_in,
                              void* d_out, int out_size)
{
    const float* x  = (const float*)d_in[0];
    const float* w1 = (const float*)d_in[1];
    const float* g1 = (const float*)d_in[2];
    const float* b1 = (const float*)d_in[3];
    const float* w2 = (const float*)d_in[4];
    const float* g2 = (const float*)d_in[5];
    const float* b2 = (const float*)d_in[6];
    float* out = (float*)d_out;

    // Resolve device-global addresses for the generic transpose
    float *p_xT, *p_w1T, *p_w2T;
    cudaGetSymbolAddress((void**)&p_xT,  g_xT);
    cudaGetSymbolAddress((void**)&p_w1T, g_w1T);
    cudaGetSymbolAddress((void**)&p_w2T, g_w2T);

    zero_stats_kernel<<<8, 256>>>();
    zero_mask_kernel<<<((size_t)MROWS * NWORD + 1023) / 1024, 1024>>>();

    // Pre-transposes: x[25088][512]->xT, w1[2048][512]->w1T, w2[512][2048]->w2T
    transpose_rc_kernel<<<dim3(MROWS / 32, CDIM / 32), dim3(32, 8)>>>(x,  p_xT,  MROWS, CDIM);
    transpose_rc_kernel<<<dim3(HDIM / 32, CDIM / 32), dim3(32, 8)>>>(w1, p_w1T, HDIM, CDIM);
    transpose_rc_kernel<<<dim3(CDIM / 32, HDIM / 32), dim3(32, 8)>>>(w2, p_w2T, CDIM, HDIM);

    // Layer 1: pipelined fp32 GEMM (bitwise chain) -> g_h1
    sgemm1_kernel<<<dim3(HDIM / BN, MROWS / BM), 256>>>();
    bn_stats_kernel<false><<<MROWS / 128, 256>>>();
    bn_final_kernel<false><<<HDIM / 256, 256>>>();
    lif1_kernel<<<((size_t)BB * NSEQ * HDIM) / 256, 256>>>(g1, b1);

    // Layer 2: sparse spike GEMM (exact no-op elision) -> g_o2
    gemm2_sparse_kernel<<<MROWS / RPC, 512>>>();
    bn_stats_kernel<true><<<MROWS / 128, 256>>>();
    bn_final_kernel<true><<<CDIM / 256, 256>>>();
    lif2_kernel<<<((size_t)BB * NSEQ * CDIM) / 256, 256>>>(g2, b2);

    transpose_out_kernel<<<dim3(7, CDIM / 32, TB_), dim3(32, 8)>>>(out);
}